// round 1
// baseline (speedup 1.0000x reference)
#include <cuda_runtime.h>
#include <cstdint>
#include <cstddef>

// Problem constants (fixed by the reference: N=256, C=2048, H=16, W=8, K=13)
#define KPT   13
#define HW    128
#define CCH   2048
#define NBAT  256
#define TC    64      // channels per CTA
#define NTHR  256     // threads per CTA (4 threads = 4 hw-quarters per channel)

// ---------- packed f32x2 helpers (Blackwell FFMA2 path) ----------
__device__ __forceinline__ unsigned long long pk2(float lo, float hi) {
    unsigned long long r;
    asm("mov.b64 %0, {%1, %2};" : "=l"(r) : "f"(lo), "f"(hi));
    return r;
}
__device__ __forceinline__ void upk2(unsigned long long v, float &lo, float &hi) {
    asm("mov.b64 {%0, %1}, %2;" : "=f"(lo), "=f"(hi) : "l"(v));
}
__device__ __forceinline__ void ffma2(unsigned long long &d,
                                      unsigned long long a,
                                      unsigned long long b) {
    asm("fma.rn.f32x2 %0, %1, %2, %0;" : "+l"(d) : "l"(a), "l"(b));
}
__device__ __forceinline__ void fadd2(unsigned long long &d, unsigned long long a) {
    asm("add.rn.f32x2 %0, %0, %1;" : "+l"(d) : "l"(a));
}

// ======================================================================
// Main kernel: one CTA = (n, 64-channel tile).
//   local[n,k,c] = sum_hw sco[n,k,hw] * feat[n,c,hw]   (k = 0..12)
//   glob[n,c]    = mean_hw feat + max_hw feat          (row 13)
// Output layout: out[n*14*2048 + row*2048 + c]
// ======================================================================
__global__ __launch_bounds__(NTHR) void horeid_feat_kernel(
    const float* __restrict__ feat,
    const float* __restrict__ sco,
    float* __restrict__ out)
{
    // feat tile: 64 rows x 33 float4 (pad 1 f4/row -> bank group = (ch+j)&7)
    __shared__ float4 sfeat[TC * 33];
    // scoremap: 13 rows x 36 f4; quarter q stored at k*36 + q*9 + j
    // -> 4 quarter-broadcast addresses hit 4 distinct bank groups
    __shared__ float4 ssco[KPT * 36];

    const int bx = blockIdx.x;
    const int n  = bx >> 5;            // 32 tiles of 64 ch per n
    const int c0 = (bx & 31) * TC;
    const int t  = threadIdx.x;

    // ---- load scoremap (13*128 floats = 416 f4), q-swizzled ----
    const float4* g_sco = reinterpret_cast<const float4*>(sco + (size_t)n * (KPT * HW));
    for (int g = t; g < KPT * 32; g += NTHR) {
        int k = g >> 5, w = g & 31;
        ssco[k * 36 + (w >> 3) * 9 + (w & 7)] = g_sco[g];
    }

    // ---- load feat tile (64*128 floats = 2048 f4), coalesced ----
    const float4* g_feat = reinterpret_cast<const float4*>(
        feat + ((size_t)n * CCH + c0) * HW);
#pragma unroll
    for (int i = 0; i < 8; ++i) {
        int g = t + i * NTHR;
        sfeat[(g >> 5) * 33 + (g & 31)] = g_feat[g];
    }
    __syncthreads();

    const int ch = t >> 2;   // channel within tile (0..63)
    const int q  = t & 3;    // hw quarter (32 elements)

    unsigned long long acc[KPT];
#pragma unroll
    for (int k = 0; k < KPT; ++k) acc[k] = 0ull;
    unsigned long long sum2 = 0ull;      // packed (0,0)
    float mx = -3.402823466e38f;

    const float4* frow = &sfeat[ch * 33 + q * 8];
    const float4* srow = &ssco[q * 9];

#pragma unroll
    for (int j = 0; j < 8; ++j) {
        float4 f = frow[j];
        unsigned long long f01 = pk2(f.x, f.y);
        unsigned long long f23 = pk2(f.z, f.w);
        fadd2(sum2, f01);
        fadd2(sum2, f23);
        mx = fmaxf(mx, fmaxf(fmaxf(f.x, f.y), fmaxf(f.z, f.w)));
#pragma unroll
        for (int k = 0; k < KPT; ++k) {
            // 16B-aligned __shared__ float4 -> safe ulonglong2 view, no movs
            const ulonglong2 s = *reinterpret_cast<const ulonglong2*>(&srow[k * 36 + j]);
            ffma2(acc[k], s.x, f01);
            ffma2(acc[k], s.y, f23);
        }
    }

    // ---- reduce the 4 quarter-lanes (lanes q, q^1, q^2 are in-warp) ----
    float res[KPT];
#pragma unroll
    for (int k = 0; k < KPT; ++k) {
        float lo, hi;
        upk2(acc[k], lo, hi);
        float r = lo + hi;
        r += __shfl_xor_sync(0xffffffffu, r, 1);
        r += __shfl_xor_sync(0xffffffffu, r, 2);
        res[k] = r;
    }
    float glob;
    {
        float lo, hi;
        upk2(sum2, lo, hi);
        float s = lo + hi;
        s += __shfl_xor_sync(0xffffffffu, s, 1);
        s += __shfl_xor_sync(0xffffffffu, s, 2);
        float m = mx;
        m = fmaxf(m, __shfl_xor_sync(0xffffffffu, m, 1));
        m = fmaxf(m, __shfl_xor_sync(0xffffffffu, m, 2));
        glob = s * (1.0f / 128.0f) + m;
    }

    // ---- writes: lane q writes rows {q, q+4, q+8, q+12}; row 13 = glob ----
    float* ob = out + (size_t)n * (14 * CCH) + (size_t)(c0 + ch);
    switch (q) {
        case 0:
            ob[0 * CCH] = res[0];  ob[4 * CCH] = res[4];
            ob[8 * CCH] = res[8];  ob[12 * CCH] = res[12];
            break;
        case 1:
            ob[1 * CCH] = res[1];  ob[5 * CCH] = res[5];
            ob[9 * CCH] = res[9];  ob[13 * CCH] = glob;
            break;
        case 2:
            ob[2 * CCH] = res[2];  ob[6 * CCH] = res[6];
            ob[10 * CCH] = res[10];
            break;
        default:
            ob[3 * CCH] = res[3];  ob[7 * CCH] = res[7];
            ob[11 * CCH] = res[11];
            break;
    }
}

// ======================================================================
// Confidence kernel: L1-normalize the 13 keypoint confidences per n,
// append 1.0 for the global slot. out2[n*14 + i].
// ======================================================================
__global__ __launch_bounds__(NBAT) void horeid_conf_kernel(
    const float* __restrict__ kc,
    float* __restrict__ out2)
{
    const int n = threadIdx.x;   // 256 threads, one per batch row
    const float* r = kc + n * KPT;
    float v[KPT];
    float s = 0.0f;
#pragma unroll
    for (int i = 0; i < KPT; ++i) {
        v[i] = r[i];
        s += fabsf(v[i]);
    }
    s = fmaxf(s, 1e-12f);
    const float inv = 1.0f / s;
    float* o = out2 + n * 14;
#pragma unroll
    for (int i = 0; i < KPT; ++i) o[i] = v[i] * inv;
    o[KPT] = 1.0f;
}

// ======================================================================
extern "C" void kernel_launch(void* const* d_in, const int* in_sizes, int n_in,
                              void* d_out, int out_size)
{
    const float* feat = nullptr;
    const float* sco  = nullptr;
    const float* kc   = nullptr;
    for (int i = 0; i < n_in; ++i) {
        if (in_sizes[i] == NBAT * CCH * HW)      feat = (const float*)d_in[i];
        else if (in_sizes[i] == NBAT * KPT * HW) sco  = (const float*)d_in[i];
        else if (in_sizes[i] == NBAT * KPT)      kc   = (const float*)d_in[i];
    }
    float* out = (float*)d_out;

    horeid_feat_kernel<<<NBAT * 32, NTHR>>>(feat, sco, out);
    horeid_conf_kernel<<<1, NBAT>>>(kc, out + (size_t)NBAT * 14 * CCH);
    (void)out_size;
}

// round 2
// speedup vs baseline: 1.1056x; 1.1056x over previous
#include <cuda_runtime.h>
#include <cstdint>
#include <cstddef>

// Problem constants (fixed by reference: N=256, C=2048, H=16, W=8, K=13)
#define KPT   13
#define HW_   128
#define CCH   2048
#define NBAT  256
#define TC    128     // channels per CTA
#define NTHR  256

typedef unsigned long long ull;

// ---------- packed f32x2 helpers (Blackwell FFMA2 path) ----------
__device__ __forceinline__ ull pk2(float lo, float hi) {
    ull r;
    asm("mov.b64 %0, {%1, %2};" : "=l"(r) : "f"(lo), "f"(hi));
    return r;
}
__device__ __forceinline__ void upk2(ull v, float &lo, float &hi) {
    asm("mov.b64 {%0, %1}, %2;" : "=f"(lo), "=f"(hi) : "l"(v));
}
__device__ __forceinline__ void ffma2(ull &d, ull a, ull b) {
    asm("fma.rn.f32x2 %0, %1, %2, %0;" : "+l"(d) : "l"(a), "l"(b));
}
__device__ __forceinline__ void fadd2(ull &d, ull a) {
    asm("add.rn.f32x2 %0, %0, %1;" : "+l"(d) : "l"(a));
}

// Dynamic smem layout:
//   [0, 65536)        feat tile: 128 ch x 32 f4, XOR-swizzled  (aliased by reduction buffer)
//   [65536, 72192)    scoremap: 13 x 32 f4
#define SMEM_BYTES 72192
extern __shared__ unsigned char smem_raw[];

// ======================================================================
// Main kernel. CTA = (n, 128-channel tile). 8 warps = 8 hw-sixteenths.
// Thread (w, l): channels {l, l+32, l+64, l+96}, hw [w*16, w*16+16).
//   local[n,k,c] = sum_hw sco[n,k,hw] * feat[n,c,hw]
//   glob[n,c]    = mean_hw feat + max_hw feat    (row 13)
// ======================================================================
__global__ __launch_bounds__(NTHR, 2) void horeid_feat_kernel(
    const float* __restrict__ feat,
    const float* __restrict__ sco,
    float* __restrict__ out)
{
    float4* sfeat = reinterpret_cast<float4*>(smem_raw);
    float4* ssco  = reinterpret_cast<float4*>(smem_raw + 65536);
    float*  red   = reinterpret_cast<float*>(smem_raw);   // alias (after sync)

    const int t  = threadIdx.x;
    const int n  = blockIdx.x >> 4;          // 16 tiles per batch row
    const int c0 = (blockIdx.x & 15) * TC;
    const int w  = t >> 5;
    const int l  = t & 31;

    // ---- load scoremap (13*128 floats = 416 f4), coalesced ----
    const float4* g_sco = reinterpret_cast<const float4*>(sco + (size_t)n * (KPT * HW_));
    for (int g = t; g < KPT * 32; g += NTHR) ssco[g] = g_sco[g];

    // ---- load feat tile (128 ch * 128 hw = 4096 f4), coalesced, XOR swizzle ----
    const float4* g_feat = reinterpret_cast<const float4*>(
        feat + ((size_t)n * CCH + c0) * HW_);
#pragma unroll
    for (int i = 0; i < 16; ++i) {
        int g  = t + i * NTHR;
        int ch = g >> 5, cl = g & 31;
        sfeat[ch * 32 + (cl ^ (ch & 7))] = g_feat[g];
    }
    __syncthreads();

    ull accA[KPT], accB[KPT];
#pragma unroll
    for (int k = 0; k < KPT; ++k) { accA[k] = 0ull; accB[k] = 0ull; }
    ull sA = 0ull, sB = 0ull;   // packed spatial sums (chLo, chHi)
    float m0 = -3.402823466e38f, m1 = m0, m2 = m0, m3 = m0;

    const int sw = l & 7;

#pragma unroll
    for (int jj = 0; jj < 4; ++jj) {
        const int col  = w * 4 + jj;     // f4 column in hw
        const int colx = col ^ sw;
        // channels l, l+32, l+64, l+96 -> same bank-group swizzle (32p = 0 mod 8)
        float4 f0 = sfeat[(l      ) * 32 + colx];
        float4 f1 = sfeat[(l + 32 ) * 32 + colx];
        float4 f2 = sfeat[(l + 64 ) * 32 + colx];
        float4 f3 = sfeat[(l + 96 ) * 32 + colx];

        ull pa0 = pk2(f0.x, f1.x), pa1 = pk2(f0.y, f1.y);
        ull pa2 = pk2(f0.z, f1.z), pa3 = pk2(f0.w, f1.w);
        ull pb0 = pk2(f2.x, f3.x), pb1 = pk2(f2.y, f3.y);
        ull pb2 = pk2(f2.z, f3.z), pb3 = pk2(f2.w, f3.w);

        fadd2(sA, pa0); fadd2(sA, pa1); fadd2(sA, pa2); fadd2(sA, pa3);
        fadd2(sB, pb0); fadd2(sB, pb1); fadd2(sB, pb2); fadd2(sB, pb3);
        m0 = fmaxf(m0, fmaxf(fmaxf(f0.x, f0.y), fmaxf(f0.z, f0.w)));
        m1 = fmaxf(m1, fmaxf(fmaxf(f1.x, f1.y), fmaxf(f1.z, f1.w)));
        m2 = fmaxf(m2, fmaxf(fmaxf(f2.x, f2.y), fmaxf(f2.z, f2.w)));
        m3 = fmaxf(m3, fmaxf(fmaxf(f3.x, f3.y), fmaxf(f3.z, f3.w)));

#pragma unroll
        for (int k = 0; k < KPT; ++k) {
            float4 s = ssco[k * 32 + col];      // uniform address across warp
            ull sx = pk2(s.x, s.x), sy = pk2(s.y, s.y);
            ull sz = pk2(s.z, s.z), sw2 = pk2(s.w, s.w);
            ffma2(accA[k], sx, pa0); ffma2(accA[k], sy, pa1);
            ffma2(accA[k], sz, pa2); ffma2(accA[k], sw2, pa3);
            ffma2(accB[k], sx, pb0); ffma2(accB[k], sy, pb1);
            ffma2(accB[k], sz, pb2); ffma2(accB[k], sw2, pb3);
        }
    }
    __syncthreads();   // everyone done reading sfeat before aliasing as red[]

    // ---- stage per-warp partials: red[(slot*8 + w)*132 + ch] ----
    // slots 0..12 = local k, 13 = spatial sum, 14 = spatial max
#pragma unroll
    for (int k = 0; k < KPT; ++k) {
        const int r = (k * 8 + w) * 132;
        float lo, hi;
        upk2(accA[k], lo, hi);  red[r + l]      = lo;  red[r + l + 32] = hi;
        upk2(accB[k], lo, hi);  red[r + l + 64] = lo;  red[r + l + 96] = hi;
    }
    {
        const int r = (13 * 8 + w) * 132;
        float lo, hi;
        upk2(sA, lo, hi);  red[r + l]      = lo;  red[r + l + 32] = hi;
        upk2(sB, lo, hi);  red[r + l + 64] = lo;  red[r + l + 96] = hi;
    }
    {
        const int r = (14 * 8 + w) * 132;
        red[r + l] = m0; red[r + l + 32] = m1; red[r + l + 64] = m2; red[r + l + 96] = m3;
    }
    __syncthreads();

    // ---- reduce 8 warp-partials and write (coalesced) ----
    float* ob = out + (size_t)n * (14 * CCH) + c0;
#pragma unroll
    for (int it = 0; it < 7; ++it) {          // 14*128 / 256 = 7
        const int idx = t + it * NTHR;
        const int s = idx >> 7, ch = idx & 127;
        if (s < 13) {
            float v = 0.0f;
#pragma unroll
            for (int w2 = 0; w2 < 8; ++w2) v += red[(s * 8 + w2) * 132 + ch];
            ob[s * CCH + ch] = v;
        } else {
            float v = 0.0f, m = -3.402823466e38f;
#pragma unroll
            for (int w2 = 0; w2 < 8; ++w2) {
                v += red[(13 * 8 + w2) * 132 + ch];
                m = fmaxf(m, red[(14 * 8 + w2) * 132 + ch]);
            }
            ob[13 * CCH + ch] = v * (1.0f / 128.0f) + m;
        }
    }
}

// ======================================================================
// Confidence kernel: L1-normalize 13 confidences per n, append 1.0.
// ======================================================================
__global__ __launch_bounds__(NBAT) void horeid_conf_kernel(
    const float* __restrict__ kc,
    float* __restrict__ out2)
{
    const int n = threadIdx.x;
    const float* r = kc + n * KPT;
    float v[KPT];
    float s = 0.0f;
#pragma unroll
    for (int i = 0; i < KPT; ++i) { v[i] = r[i]; s += fabsf(v[i]); }
    s = fmaxf(s, 1e-12f);
    const float inv = 1.0f / s;
    float* o = out2 + n * 14;
#pragma unroll
    for (int i = 0; i < KPT; ++i) o[i] = v[i] * inv;
    o[KPT] = 1.0f;
}

// ======================================================================
extern "C" void kernel_launch(void* const* d_in, const int* in_sizes, int n_in,
                              void* d_out, int out_size)
{
    const float* feat = nullptr;
    const float* sco  = nullptr;
    const float* kc   = nullptr;
    for (int i = 0; i < n_in; ++i) {
        if (in_sizes[i] == NBAT * CCH * HW_)      feat = (const float*)d_in[i];
        else if (in_sizes[i] == NBAT * KPT * HW_) sco  = (const float*)d_in[i];
        else if (in_sizes[i] == NBAT * KPT)       kc   = (const float*)d_in[i];
    }
    float* out = (float*)d_out;

    static bool attr_done = false;  // attribute set is idempotent & deterministic
    cudaFuncSetAttribute(horeid_feat_kernel,
                         cudaFuncAttributeMaxDynamicSharedMemorySize, SMEM_BYTES);
    (void)attr_done;

    // conf first so ncu (-s 5 -c 1) lands on the main kernel
    horeid_conf_kernel<<<1, NBAT>>>(kc, out + (size_t)NBAT * 14 * CCH);
    horeid_feat_kernel<<<NBAT * 16, NTHR, SMEM_BYTES>>>(feat, sco, out);
    (void)out_size;
}

// round 3
// speedup vs baseline: 1.7415x; 1.5752x over previous
#include <cuda_runtime.h>
#include <cstdint>
#include <cstddef>

// Problem constants (fixed by reference: N=256, C=2048, H=16, W=8, K=13)
#define KPT   13
#define HW_   128
#define CCH   2048
#define NBAT  256
#define TC    128     // channels per CTA
#define NTHR  256

typedef unsigned long long ull;

__device__ __forceinline__ void upk2(ull v, float &lo, float &hi) {
    asm("mov.b64 {%0, %1}, %2;" : "=f"(lo), "=f"(hi) : "l"(v));
}
__device__ __forceinline__ void ffma2(ull &d, ull a, ull b) {
    asm("fma.rn.f32x2 %0, %1, %2, %0;" : "+l"(d) : "l"(a), "l"(b));
}
__device__ __forceinline__ void fadd2(ull &d, ull a) {
    asm("add.rn.f32x2 %0, %0, %1;" : "+l"(d) : "l"(a));
}

// Dynamic smem layout:
//   [0, 65536)        feat tile: 128 ch x 32 f4, XOR-swizzled (aliased by red buf)
//   [65536, 72192)    scoremap: 13 x 32 f4
#define SMEM_BYTES 72192
extern __shared__ unsigned char smem_raw[];

// ======================================================================
// CTA = (n, 128-channel tile). Thread (cp = t&63, s = t>>6):
//   channels {2cp, 2cp+1}, hw slice [s*32, s*32+32).
// f32x2 lanes = (even hw, odd hw) -> all FFMA2 operands come straight
// from LDS.128 register pairs, no packing movs.
// ======================================================================
__global__ __launch_bounds__(NTHR, 3) void horeid_feat_kernel(
    const float* __restrict__ feat,
    const float* __restrict__ sco,
    float* __restrict__ out)
{
    float4* sfeat = reinterpret_cast<float4*>(smem_raw);
    float4* ssco  = reinterpret_cast<float4*>(smem_raw + 65536);
    float2* red2  = reinterpret_cast<float2*>(smem_raw);   // alias after sync
    float*  red   = reinterpret_cast<float*>(smem_raw);

    const int t  = threadIdx.x;
    const int n  = blockIdx.x >> 4;          // 16 tiles per batch row
    const int c0 = (blockIdx.x & 15) * TC;
    const int cp = t & 63;                   // channel pair index (0..63)
    const int s  = t >> 6;                   // hw slice (0..3)

    // ---- load scoremap (416 f4), coalesced ----
    const float4* g_sco = reinterpret_cast<const float4*>(sco + (size_t)n * (KPT * HW_));
    for (int g = t; g < KPT * 32; g += NTHR) ssco[g] = g_sco[g];

    // ---- load feat tile (4096 f4), coalesced, swizzle col ^ ((ch>>1)&7) ----
    const float4* g_feat = reinterpret_cast<const float4*>(
        feat + ((size_t)n * CCH + c0) * HW_);
#pragma unroll
    for (int i = 0; i < 16; ++i) {
        int g  = t + i * NTHR;
        int ch = g >> 5, cl = g & 31;
        sfeat[ch * 32 + (cl ^ ((ch >> 1) & 7))] = g_feat[g];
    }
    __syncthreads();

    ull acc0[KPT], acc1[KPT];
#pragma unroll
    for (int k = 0; k < KPT; ++k) { acc0[k] = 0ull; acc1[k] = 0ull; }
    ull sum0 = 0ull, sum1 = 0ull;
    float mx0 = -3.402823466e38f, mx1 = mx0;

    const float4* fr0 = &sfeat[(2 * cp    ) * 32];
    const float4* fr1 = &sfeat[(2 * cp + 1) * 32];
    const int swz = cp & 7;

#pragma unroll
    for (int jj = 0; jj < 8; ++jj) {
        const int j    = s * 8 + jj;     // f4 column (warp-uniform)
        const int colx = j ^ swz;

        float4 f0 = fr0[colx];
        float4 f1 = fr1[colx];
        // ull views of the loaded register pairs (no movs)
        ull a0 = reinterpret_cast<ull*>(&f0)[0];
        ull a1 = reinterpret_cast<ull*>(&f0)[1];
        ull b0 = reinterpret_cast<ull*>(&f1)[0];
        ull b1 = reinterpret_cast<ull*>(&f1)[1];

        fadd2(sum0, a0); fadd2(sum0, a1);
        fadd2(sum1, b0); fadd2(sum1, b1);
        mx0 = fmaxf(mx0, fmaxf(fmaxf(f0.x, f0.y), fmaxf(f0.z, f0.w)));
        mx1 = fmaxf(mx1, fmaxf(fmaxf(f1.x, f1.y), fmaxf(f1.z, f1.w)));

#pragma unroll
        for (int k = 0; k < KPT; ++k) {
            float4 sv = ssco[k * 32 + j];         // uniform broadcast
            ull s01 = reinterpret_cast<ull*>(&sv)[0];
            ull s23 = reinterpret_cast<ull*>(&sv)[1];
            ffma2(acc0[k], s01, a0); ffma2(acc0[k], s23, a1);
            ffma2(acc1[k], s01, b0); ffma2(acc1[k], s23, b1);
        }
    }
    __syncthreads();   // done reading sfeat; alias as reduction buffer

    // ---- stage partials: red2[slot*256 + s*64 + cp] = (ch0, ch1) ----
    // slots 0..12 local k, 13 spatial sum, 14 spatial max
#pragma unroll
    for (int k = 0; k < KPT; ++k) {
        float l0, h0, l1, h1;
        upk2(acc0[k], l0, h0);
        upk2(acc1[k], l1, h1);
        red2[k * 256 + s * 64 + cp] = make_float2(l0 + h0, l1 + h1);
    }
    {
        float l0, h0, l1, h1;
        upk2(sum0, l0, h0);
        upk2(sum1, l1, h1);
        red2[13 * 256 + s * 64 + cp] = make_float2(l0 + h0, l1 + h1);
        red2[14 * 256 + s * 64 + cp] = make_float2(mx0, mx1);
    }
    __syncthreads();

    // ---- fold 4 slices, write coalesced ----
    float* ob = out + (size_t)n * (14 * CCH) + c0;
#pragma unroll
    for (int it = 0; it < 7; ++it) {          // 14*128/256 = 7
        const int idx  = t + it * NTHR;
        const int slot = idx >> 7, ch = idx & 127;
        if (slot < 13) {
            float v = red[slot * 512 + ch] + red[slot * 512 + 128 + ch]
                    + red[slot * 512 + 256 + ch] + red[slot * 512 + 384 + ch];
            ob[slot * CCH + ch] = v;
        } else {
            float v = red[13 * 512 + ch] + red[13 * 512 + 128 + ch]
                    + red[13 * 512 + 256 + ch] + red[13 * 512 + 384 + ch];
            float m = fmaxf(fmaxf(red[14 * 512 + ch],       red[14 * 512 + 128 + ch]),
                            fmaxf(red[14 * 512 + 256 + ch], red[14 * 512 + 384 + ch]));
            ob[13 * CCH + ch] = v * (1.0f / 128.0f) + m;
        }
    }
}

// ======================================================================
// Confidence kernel: L1-normalize 13 confidences per n, append 1.0.
// ======================================================================
__global__ __launch_bounds__(NBAT) void horeid_conf_kernel(
    const float* __restrict__ kc,
    float* __restrict__ out2)
{
    const int n = threadIdx.x;
    const float* r = kc + n * KPT;
    float v[KPT];
    float sm = 0.0f;
#pragma unroll
    for (int i = 0; i < KPT; ++i) { v[i] = r[i]; sm += fabsf(v[i]); }
    sm = fmaxf(sm, 1e-12f);
    const float inv = 1.0f / sm;
    float* o = out2 + n * 14;
#pragma unroll
    for (int i = 0; i < KPT; ++i) o[i] = v[i] * inv;
    o[KPT] = 1.0f;
}

// ======================================================================
extern "C" void kernel_launch(void* const* d_in, const int* in_sizes, int n_in,
                              void* d_out, int out_size)
{
    const float* feat = nullptr;
    const float* sco  = nullptr;
    const float* kc   = nullptr;
    for (int i = 0; i < n_in; ++i) {
        if (in_sizes[i] == NBAT * CCH * HW_)      feat = (const float*)d_in[i];
        else if (in_sizes[i] == NBAT * KPT * HW_) sco  = (const float*)d_in[i];
        else if (in_sizes[i] == NBAT * KPT)       kc   = (const float*)d_in[i];
    }
    float* out = (float*)d_out;

    cudaFuncSetAttribute(horeid_feat_kernel,
                         cudaFuncAttributeMaxDynamicSharedMemorySize, SMEM_BYTES);

    // conf first so ncu (-s 5 -c 1) lands on the main kernel
    horeid_conf_kernel<<<1, NBAT>>>(kc, out + (size_t)NBAT * 14 * CCH);
    horeid_feat_kernel<<<NBAT * 16, NTHR, SMEM_BYTES>>>(feat, sco, out);
    (void)out_size;
}

// round 9
// speedup vs baseline: 2.2615x; 1.2986x over previous
#include <cuda_runtime.h>
#include <cstdint>
#include <cstddef>

// Problem constants (fixed by reference: N=256, C=2048, H=16, W=8, K=13)
#define KPT   13
#define HW_   128
#define CCH   2048
#define NBAT  256
#define TC    64      // channels per CTA
#define NTHR  256

typedef unsigned long long ull;

__device__ __forceinline__ void upk2(ull v, float &lo, float &hi) {
    asm("mov.b64 {%0, %1}, %2;" : "=f"(lo), "=f"(hi) : "l"(v));
}
__device__ __forceinline__ void ffma2(ull &d, ull a, ull b) {
    asm("fma.rn.f32x2 %0, %1, %2, %0;" : "+l"(d) : "l"(a), "l"(b));
}
__device__ __forceinline__ void fadd2(ull &d, ull a) {
    asm("add.rn.f32x2 %0, %0, %1;" : "+l"(d) : "l"(a));
}
__device__ __forceinline__ void cp16(uint32_t dst, const void* src) {
    asm volatile("cp.async.cg.shared.global [%0], [%1], 16;\n" :: "r"(dst), "l"(src));
}

// Static smem (39.4 KB < 48 KB default — no attribute call needed):
//   [0,32768)       feat 64ch x 32 f4 swizzled (aliased by red buf)
//   [32768, 39424)  score 13 x 32 f4
struct SmemLayout {
    float4 sfeat[TC * 32];
    float4 ssco[KPT * 32];
};

// ======================================================================
// CTA = (n, 64-channel tile). 8 warps: warps 0-3 -> k in [0,7),
// warps 4-7 -> k in [7,13). Thread (kg, sl, cp):
//   channels {2cp, 2cp+1}, hw slice [sl*32, sl*32+32), k-subset kg.
// f32x2 lanes = adjacent hw pairs straight from LDS.128 register pairs.
// ======================================================================
__global__ __launch_bounds__(NTHR, 4) void horeid_feat_kernel(
    const float* __restrict__ feat,
    const float* __restrict__ sco,
    float* __restrict__ out)
{
    __shared__ SmemLayout sm;
    float4* sfeat = sm.sfeat;
    float4* ssco  = sm.ssco;
    float2* red2  = reinterpret_cast<float2*>(sm.sfeat);   // alias after sync
    float*  red   = reinterpret_cast<float*>(sm.sfeat);

    const int t  = threadIdx.x;
    const int n  = blockIdx.x >> 5;          // 32 tiles per batch row
    const int c0 = (blockIdx.x & 31) * TC;
    const int kg = t >> 7;                   // k-group (warp-uniform)
    const int sl = (t >> 5) & 3;             // hw slice   (warp-uniform)
    const int cp = t & 31;                   // channel pair (lane)
    const int kbase = kg * 7;
    const int kn    = kg ? 6 : 7;

    const uint32_t fbase = (uint32_t)__cvta_generic_to_shared(sm.sfeat);
    const uint32_t scb   = (uint32_t)__cvta_generic_to_shared(sm.ssco);

    // ---- async load scoremap (416 f4) ----
    const float4* g_sco = reinterpret_cast<const float4*>(sco + (size_t)n * (KPT * HW_));
    for (int g = t; g < KPT * 32; g += NTHR)
        cp16(scb + (uint32_t)g * 16u, g_sco + g);

    // ---- async load feat tile (2048 f4), swizzle col ^ ((ch>>1)&7) ----
    const float4* g_feat = reinterpret_cast<const float4*>(
        feat + ((size_t)n * CCH + c0) * HW_);
#pragma unroll
    for (int i = 0; i < 8; ++i) {
        int g  = t + i * NTHR;
        int ch = g >> 5, cl = g & 31;
        cp16(fbase + (uint32_t)(ch * 32 + (cl ^ ((ch >> 1) & 7))) * 16u, g_feat + g);
    }
    asm volatile("cp.async.commit_group;\n");
    asm volatile("cp.async.wait_group 0;\n");
    __syncthreads();

    ull acc0[7], acc1[7];
#pragma unroll
    for (int kk = 0; kk < 7; ++kk) { acc0[kk] = 0ull; acc1[kk] = 0ull; }
    ull sum0 = 0ull, sum1 = 0ull;
    float mx0 = -3.402823466e38f, mx1 = mx0;

    const float4* fr0 = &sfeat[(2 * cp) * 32];
    const float4* fr1 = fr0 + 32;
    const int swz = cp & 7;

#pragma unroll
    for (int jj = 0; jj < 8; ++jj) {
        const int j    = sl * 8 + jj;        // f4 column (warp-uniform)
        const int colx = j ^ swz;

        float4 f0 = fr0[colx];
        float4 f1 = fr1[colx];
        ull a0 = reinterpret_cast<ull*>(&f0)[0];
        ull a1 = reinterpret_cast<ull*>(&f0)[1];
        ull b0 = reinterpret_cast<ull*>(&f1)[0];
        ull b1 = reinterpret_cast<ull*>(&f1)[1];

        if (kg == 0) {                        // warp-uniform branch
            fadd2(sum0, a0); fadd2(sum0, a1);
            fadd2(sum1, b0); fadd2(sum1, b1);
            mx0 = fmaxf(mx0, fmaxf(fmaxf(f0.x, f0.y), fmaxf(f0.z, f0.w)));
            mx1 = fmaxf(mx1, fmaxf(fmaxf(f1.x, f1.y), fmaxf(f1.z, f1.w)));
        }

#pragma unroll
        for (int kk = 0; kk < 7; ++kk) {
            if (kk < kn) {                    // warp-uniform predicate
                float4 sv = ssco[(kbase + kk) * 32 + j];   // uniform broadcast
                ull s01 = reinterpret_cast<ull*>(&sv)[0];
                ull s23 = reinterpret_cast<ull*>(&sv)[1];
                ffma2(acc0[kk], s01, a0); ffma2(acc0[kk], s23, a1);
                ffma2(acc1[kk], s01, b0); ffma2(acc1[kk], s23, b1);
            }
        }
    }
    __syncthreads();   // done reading sfeat; alias as reduction buffer

    // ---- stage partials: red2[slot*128 + sl*32 + cp] = (ch0, ch1) ----
    // slots 0..12 local k, 13 spatial sum, 14 spatial max
#pragma unroll
    for (int kk = 0; kk < 7; ++kk) {
        if (kk < kn) {
            float l0, h0, l1, h1;
            upk2(acc0[kk], l0, h0);
            upk2(acc1[kk], l1, h1);
            red2[(kbase + kk) * 128 + sl * 32 + cp] = make_float2(l0 + h0, l1 + h1);
        }
    }
    if (kg == 0) {
        float l0, h0, l1, h1;
        upk2(sum0, l0, h0);
        upk2(sum1, l1, h1);
        red2[13 * 128 + sl * 32 + cp] = make_float2(l0 + h0, l1 + h1);
        red2[14 * 128 + sl * 32 + cp] = make_float2(mx0, mx1);
    }
    __syncthreads();

    // ---- fold 4 slices, write coalesced (14*64 = 896 outputs) ----
    float* ob = out + (size_t)n * (14 * CCH) + c0;
#pragma unroll
    for (int it = 0; it < 4; ++it) {
        const int idx = t + it * NTHR;
        if (idx < 14 * TC) {
            const int slot = idx >> 6, ch = idx & 63;
            if (slot < 13) {
                float v = red[slot * 256 + ch]       + red[slot * 256 + 64 + ch]
                        + red[slot * 256 + 128 + ch] + red[slot * 256 + 192 + ch];
                ob[slot * CCH + ch] = v;
            } else {
                float v = red[13 * 256 + ch]       + red[13 * 256 + 64 + ch]
                        + red[13 * 256 + 128 + ch] + red[13 * 256 + 192 + ch];
                float m = fmaxf(fmaxf(red[14 * 256 + ch],       red[14 * 256 + 64 + ch]),
                                fmaxf(red[14 * 256 + 128 + ch], red[14 * 256 + 192 + ch]));
                ob[13 * CCH + ch] = v * (1.0f / 128.0f) + m;
            }
        }
    }
}

// ======================================================================
// Confidence kernel: L1-normalize 13 confidences per n, append 1.0.
// ======================================================================
__global__ __launch_bounds__(NBAT) void horeid_conf_kernel(
    const float* __restrict__ kc,
    float* __restrict__ out2)
{
    const int n = threadIdx.x;
    const float* r = kc + n * KPT;
    float v[KPT];
    float sm = 0.0f;
#pragma unroll
    for (int i = 0; i < KPT; ++i) { v[i] = r[i]; sm += fabsf(v[i]); }
    sm = fmaxf(sm, 1e-12f);
    const float inv = 1.0f / sm;
    float* o = out2 + n * 14;
#pragma unroll
    for (int i = 0; i < KPT; ++i) o[i] = v[i] * inv;
    o[KPT] = 1.0f;
}

// ======================================================================
extern "C" void kernel_launch(void* const* d_in, const int* in_sizes, int n_in,
                              void* d_out, int out_size)
{
    const float* feat = nullptr;
    const float* sco  = nullptr;
    const float* kc   = nullptr;
    for (int i = 0; i < n_in; ++i) {
        if (in_sizes[i] == NBAT * CCH * HW_)      feat = (const float*)d_in[i];
        else if (in_sizes[i] == NBAT * KPT * HW_) sco  = (const float*)d_in[i];
        else if (in_sizes[i] == NBAT * KPT)       kc   = (const float*)d_in[i];
    }
    float* out = (float*)d_out;

    // conf first so ncu (-s 5 -c 1) lands on the main kernel
    horeid_conf_kernel<<<1, NBAT>>>(kc, out + (size_t)NBAT * 14 * CCH);
    horeid_feat_kernel<<<NBAT * 32, NTHR>>>(feat, sco, out);
    (void)out_size;
}